// round 15
// baseline (speedup 1.0000x reference)
#include <cuda_runtime.h>
#include <cstdint>
#include <cstddef>

#define NN     50000
#define HID    64
#define EMAX   800000
#define IN_DIM 512
#define SCAN_B 256

// ---------------------------------------------------------------------------
// Scratch (__device__ globals; no allocation allowed)
// ---------------------------------------------------------------------------
__device__ __align__(256) float g_dinv[NN];
__device__ int   g_cnt[NN];
__device__ int   g_rowptr[NN + 1];
__device__ int   g_cursor[NN];
__device__ int   g_col[EMAX];
__device__ int   g_bsum[(NN + SCAN_B - 1) / SCAN_B];
__device__ __align__(256) float g_w1t[IN_DIM * HID];   // W1 as tf32 bits (RNA)
__device__ __align__(256) float g_w2t[HID * HID];      // W2 as tf32 bits (RNA)
__device__ __align__(256) float g_bufA[NN * HID];
__device__ __align__(256) float g_bufB[NN * HID];

__device__ __forceinline__ uint32_t cvt_tf32(float x) {
    uint32_t r;
    asm("cvt.rna.tf32.f32 %0, %1;" : "=r"(r) : "f"(x));
    return r;
}

// ---------------------------------------------------------------------------
// k_init: zero cnt + pre-convert W1/W2 to tf32 (merged independent work)
// ---------------------------------------------------------------------------
__global__ void k_init(int* cnt, const float* __restrict__ W1,
                       const float* __restrict__ W2,
                       float* w1t, float* w2t, int n) {
    int i = blockIdx.x * blockDim.x + threadIdx.x;
    if (i < n) cnt[i] = 0;
    if (i < IN_DIM * HID) w1t[i] = __uint_as_float(cvt_tf32(W1[i]));
    if (i < HID * HID)    w2t[i] = __uint_as_float(cvt_tf32(W2[i]));
}

// ---------------------------------------------------------------------------
// k_count: degree count, int4-vectorized dst reads (4 edges/thread)
// ---------------------------------------------------------------------------
__global__ void k_count(const int* __restrict__ dst, int* cnt, int E) {
    int i = blockIdx.x * blockDim.x + threadIdx.x;
    int e0 = i * 4;
    if (e0 + 3 < E) {
        int4 d = *(const int4*)(dst + e0);
        atomicAdd(&cnt[d.x], 1);
        atomicAdd(&cnt[d.y], 1);
        atomicAdd(&cnt[d.z], 1);
        atomicAdd(&cnt[d.w], 1);
    } else {
        for (int e = e0; e < E; e++) atomicAdd(&cnt[dst[e]], 1);
    }
}

// ---------------------------------------------------------------------------
// k_prep2: dinv = rsqrt(cnt+1) AND per-block sums of cnt (s1 merged)
// ---------------------------------------------------------------------------
__global__ void __launch_bounds__(SCAN_B)
k_prep2(const int* __restrict__ cnt, float* dinv, int* bsum, int n) {
    int i = blockIdx.x * SCAN_B + threadIdx.x;
    int v = (i < n) ? cnt[i] : 0;
    if (i < n) dinv[i] = rsqrtf((float)(v + 1));
#pragma unroll
    for (int d = 16; d > 0; d >>= 1) v += __shfl_down_sync(0xffffffffu, v, d);
    __shared__ int ws[8];
    int lane = threadIdx.x & 31, wid = threadIdx.x >> 5;
    if (lane == 0) ws[wid] = v;
    __syncthreads();
    if (wid == 0) {
        int s = (lane < 8) ? ws[lane] : 0;
#pragma unroll
        for (int d = 4; d > 0; d >>= 1) s += __shfl_down_sync(0xffffffffu, s, d);
        if (lane == 0) bsum[blockIdx.x] = s;
    }
}

// ---------------------------------------------------------------------------
// S3: each block re-scans bsum locally, then block-local exclusive scan of cnt.
// ---------------------------------------------------------------------------
__global__ void __launch_bounds__(SCAN_B)
k_s3(const int* __restrict__ cnt, const int* __restrict__ bsum,
     int* rowptr, int* cursor, int nb, int n) {
    __shared__ int sb[SCAN_B];
    __shared__ int wsA[8], wsB[8];
    const int t = threadIdx.x;
    const int lane = t & 31, wid = t >> 5;

    int bv = (t < nb) ? bsum[t] : 0;
    int inc1 = bv;
#pragma unroll
    for (int d = 1; d < 32; d <<= 1) {
        int u = __shfl_up_sync(0xffffffffu, inc1, d);
        if (lane >= d) inc1 += u;
    }
    if (lane == 31) wsA[wid] = inc1;
    __syncthreads();
    if (wid == 0 && lane < 8) {
        int w = wsA[lane];
#pragma unroll
        for (int d = 1; d < 8; d <<= 1) {
            int u = __shfl_up_sync(0xffu, w, d);
            if (lane >= d) w += u;
        }
        wsA[lane] = w;
    }
    __syncthreads();
    sb[t] = inc1 + (wid > 0 ? wsA[wid - 1] : 0);
    __syncthreads();

    int base = (blockIdx.x > 0) ? sb[blockIdx.x - 1] : 0;
    if (blockIdx.x == 0 && t == 0) rowptr[n] = sb[nb - 1];

    int i = blockIdx.x * SCAN_B + t;
    int c = (i < n) ? cnt[i] : 0;
    int inc2 = c;
#pragma unroll
    for (int d = 1; d < 32; d <<= 1) {
        int u = __shfl_up_sync(0xffffffffu, inc2, d);
        if (lane >= d) inc2 += u;
    }
    if (lane == 31) wsB[wid] = inc2;
    __syncthreads();
    if (wid == 0 && lane < 8) {
        int w = wsB[lane];
#pragma unroll
        for (int d = 1; d < 8; d <<= 1) {
            int u = __shfl_up_sync(0xffu, w, d);
            if (lane >= d) w += u;
        }
        wsB[lane] = w;
    }
    __syncthreads();
    int excl = inc2 - c + (wid > 0 ? wsB[wid - 1] : 0) + base;
    if (i < n) {
        rowptr[i] = excl;
        cursor[i] = excl;
    }
}

// ---------------------------------------------------------------------------
// k_fill: CSR fill, int4-vectorized src/dst reads (4 edges/thread)
// ---------------------------------------------------------------------------
__global__ void k_fill(const int* __restrict__ src, const int* __restrict__ dst,
                       int* cursor, int* col, int E) {
    int i = blockIdx.x * blockDim.x + threadIdx.x;
    int e0 = i * 4;
    if (e0 + 3 < E) {
        int4 d = *(const int4*)(dst + e0);
        int4 s = *(const int4*)(src + e0);
        col[atomicAdd(&cursor[d.x], 1)] = s.x;
        col[atomicAdd(&cursor[d.y], 1)] = s.y;
        col[atomicAdd(&cursor[d.z], 1)] = s.z;
        col[atomicAdd(&cursor[d.w], 1)] = s.w;
    } else {
        for (int e = e0; e < E; e++)
            col[atomicAdd(&cursor[dst[e]], 1)] = src[e];
    }
}

// ---------------------------------------------------------------------------
// tf32 tensor-core GEMM, cp.async 2-stage, BM=64/BK=32, 128 threads.
//   hn = (X @ W) * dinv[row]  (pre-scaled)
// W pre-converted (RNA); A uses RAW fp32 bits as tf32 (truncation) — no cvt.
// ---------------------------------------------------------------------------
#define BM 64
#define BKG 32
#define PA 36
#define PB 72

template <int K>
__global__ void __launch_bounds__(128)
k_gemm(const float* __restrict__ X, const float* __restrict__ Wt,
       const float* __restrict__ dinv, float* __restrict__ hn, int M) {
    __shared__ float as[2 * BM * PA];
    __shared__ float ws[2 * BKG * PB];

    const int t    = threadIdx.x;
    const int m0   = blockIdx.x * BM;
    const int lane = t & 31;
    const int wid  = t >> 5;
    const int wm   = wid >> 1;
    const int wn   = wid & 1;
    const int g    = lane >> 2;
    const int tig  = lane & 3;

    float c[2][4][4];
#pragma unroll
    for (int mt = 0; mt < 2; mt++)
#pragma unroll
        for (int nt = 0; nt < 4; nt++)
#pragma unroll
            for (int i = 0; i < 4; i++) c[mt][nt][i] = 0.0f;

    auto load_stage = [&](int buf, int k0) {
        float* asb = as + buf * BM * PA;
        float* wsb = ws + buf * BKG * PB;
#pragma unroll
        for (int i = 0; i < 4; i++) {
            int G = i * 128 + t;
            int row = G >> 3, gg = G & 7;
            bool ok = (m0 + row) < M;
            const float* gp = ok ? (X + (size_t)(m0 + row) * K + k0 + gg * 4) : X;
            uint32_t sa = (uint32_t)__cvta_generic_to_shared(asb + row * PA + gg * 4);
            int sz = ok ? 16 : 0;
            asm volatile("cp.async.cg.shared.global [%0], [%1], 16, %2;\n"
                         :: "r"(sa), "l"(gp), "r"(sz));
        }
#pragma unroll
        for (int i = 0; i < 4; i++) {
            int G = i * 128 + t;
            int kr = G >> 4, gn = G & 15;
            const float* gp = Wt + (size_t)(k0 + kr) * 64 + gn * 4;
            uint32_t sa = (uint32_t)__cvta_generic_to_shared(wsb + kr * PB + gn * 4);
            asm volatile("cp.async.cg.shared.global [%0], [%1], 16;\n"
                         :: "r"(sa), "l"(gp));
        }
    };

    load_stage(0, 0);
    asm volatile("cp.async.commit_group;\n");

    const int NIT = K / BKG;
    for (int it = 0; it < NIT; it++) {
        if (it + 1 < NIT) load_stage((it + 1) & 1, (it + 1) * BKG);
        asm volatile("cp.async.commit_group;\n");
        asm volatile("cp.async.wait_group 1;\n");
        __syncthreads();

        const float* asb = as + (it & 1) * BM * PA;
        const float* wsb = ws + (it & 1) * BKG * PB;

#pragma unroll
        for (int ks = 0; ks < BKG; ks += 8) {
            uint32_t a[2][4], b[4][2];
#pragma unroll
            for (int mt = 0; mt < 2; mt++) {
                int r = wm * 32 + mt * 16 + g;
                a[mt][0] = __float_as_uint(asb[r * PA + ks + tig]);        // raw tf32
                a[mt][1] = __float_as_uint(asb[(r + 8) * PA + ks + tig]);
                a[mt][2] = __float_as_uint(asb[r * PA + ks + tig + 4]);
                a[mt][3] = __float_as_uint(asb[(r + 8) * PA + ks + tig + 4]);
            }
#pragma unroll
            for (int nt = 0; nt < 4; nt++) {
                int n = wn * 32 + nt * 8 + g;
                b[nt][0] = __float_as_uint(wsb[(ks + tig) * PB + n]);      // pre-cvt'd
                b[nt][1] = __float_as_uint(wsb[(ks + tig + 4) * PB + n]);
            }
#pragma unroll
            for (int mt = 0; mt < 2; mt++)
#pragma unroll
                for (int nt = 0; nt < 4; nt++) {
                    asm volatile(
                        "mma.sync.aligned.m16n8k8.row.col.f32.tf32.tf32.f32 "
                        "{%0,%1,%2,%3}, {%4,%5,%6,%7}, {%8,%9}, {%0,%1,%2,%3};"
                        : "+f"(c[mt][nt][0]), "+f"(c[mt][nt][1]),
                          "+f"(c[mt][nt][2]), "+f"(c[mt][nt][3])
                        : "r"(a[mt][0]), "r"(a[mt][1]), "r"(a[mt][2]), "r"(a[mt][3]),
                          "r"(b[nt][0]), "r"(b[nt][1]));
                }
        }
        __syncthreads();
    }

    // --- epilogue: hn = acc * dinv[row]
#pragma unroll
    for (int mt = 0; mt < 2; mt++) {
        int rbase = m0 + wm * 32 + mt * 16 + g;
#pragma unroll
        for (int half = 0; half < 2; half++) {
            int row = rbase + half * 8;
            if (row < M) {
                float s = __ldg(&dinv[row]);
#pragma unroll
                for (int nt = 0; nt < 4; nt++) {
                    float2 v;
                    v.x = c[mt][nt][half * 2 + 0] * s;
                    v.y = c[mt][nt][half * 2 + 1] * s;
                    *(float2*)(hn + (size_t)row * 64 + wn * 32 + nt * 8 + 2 * tig) = v;
                }
            }
        }
    }
}

// ---------------------------------------------------------------------------
// Fused aggregate (warp per node, hn pre-scaled, float2 lanes, 1 LDG.64/edge)
// ---------------------------------------------------------------------------
template <bool RELU>
__global__ void __launch_bounds__(256)
k_agg(const int* __restrict__ rowptr, const int* __restrict__ col,
      const float2* __restrict__ hn2, const float* __restrict__ dinv,
      const float2* __restrict__ bias2, float2* __restrict__ out2, int n) {
    int w = (blockIdx.x * blockDim.x + threadIdx.x) >> 5;
    int lane = threadIdx.x & 31;
    if (w >= n) return;

    float2 acc = __ldg(&hn2[(size_t)w * 32 + lane]);

    int beg = __ldg(&rowptr[w]);
    int end = __ldg(&rowptr[w + 1]);

    for (int e0 = beg; e0 < end; e0 += 16) {
        int idx = e0 + (lane & 15);
        int cs = (idx < end) ? __ldg(&col[idx]) : -1;
#pragma unroll
        for (int j = 0; j < 16; j++) {
            int s = __shfl_sync(0xffffffffu, cs, j);
            if (s >= 0) {
                float2 v = __ldg(&hn2[(size_t)s * 32 + lane]);
                acc.x += v.x;
                acc.y += v.y;
            }
        }
    }

    float di = __ldg(&dinv[w]);
    float2 b = __ldg(&bias2[lane]);
    float2 v;
    v.x = di * acc.x + b.x;
    v.y = di * acc.y + b.y;
    if (RELU) { v.x = fmaxf(v.x, 0.0f); v.y = fmaxf(v.y, 0.0f); }
    out2[(size_t)w * 32 + lane] = v;
}

// ---------------------------------------------------------------------------
// Launch (serial, 9 kernels; GEMM1 at slot #4 for profiling consistency)
// ---------------------------------------------------------------------------
extern "C" void kernel_launch(void* const* d_in, const int* in_sizes, int n_in,
                              void* d_out, int out_size) {
    const float* x  = (const float*)d_in[0];
    const int*   ei = (const int*)d_in[1];
    const float* W1 = (const float*)d_in[2];
    const float* b1 = (const float*)d_in[3];
    const float* W2 = (const float*)d_in[4];
    const float* b2 = (const float*)d_in[5];

    const int E = in_sizes[1] / 2;
    const int M = out_size / HID;
    const int* src = ei;
    const int* dst = ei + E;

    float *dinv, *bufA, *bufB, *w1t, *w2t;
    int *cnt, *rowptr, *cursor, *col, *bsum;
    cudaGetSymbolAddress((void**)&dinv,   g_dinv);
    cudaGetSymbolAddress((void**)&cnt,    g_cnt);
    cudaGetSymbolAddress((void**)&rowptr, g_rowptr);
    cudaGetSymbolAddress((void**)&cursor, g_cursor);
    cudaGetSymbolAddress((void**)&col,    g_col);
    cudaGetSymbolAddress((void**)&bsum,   g_bsum);
    cudaGetSymbolAddress((void**)&w1t,    g_w1t);
    cudaGetSymbolAddress((void**)&w2t,    g_w2t);
    cudaGetSymbolAddress((void**)&bufA,   g_bufA);
    cudaGetSymbolAddress((void**)&bufB,   g_bufB);
    float* out = (float*)d_out;

    const int gblk = (M + BM - 1) / BM;
    const int ablk = (M * 32 + 255) / 256;
    const int nb   = (M + SCAN_B - 1) / SCAN_B;
    const int eblk = (E / 4 + 255) / 256;

    // 1. init (zero cnt + W tf32 convert)
    k_init<<<(M + 255) / 256, 256>>>(cnt, W1, W2, w1t, w2t, M);
    // 2. degree count (int4)
    k_count<<<eblk, 256>>>(dst, cnt, E);
    // 3. dinv + per-block sums
    k_prep2<<<nb, SCAN_B>>>(cnt, dinv, bsum, M);
    // 4. GEMM1 (slot #4): hn1 = (x@W1)*dinv -> bufA
    k_gemm<IN_DIM><<<gblk, 128>>>(x, w1t, dinv, bufA, M);
    // 5-6. scan + fill (int4)
    k_s3<<<nb, SCAN_B>>>(cnt, bsum, rowptr, cursor, nb, M);
    k_fill<<<eblk, 256>>>(src, dst, cursor, col, E);
    // 7. agg1 (+bias1, ReLU) -> bufB
    k_agg<true><<<ablk, 256>>>(rowptr, col, (const float2*)bufA, dinv,
                               (const float2*)b1, (float2*)bufB, M);
    // 8-9. GEMM2 -> bufA ; agg2 (+bias2) -> out
    k_gemm<HID><<<gblk, 128>>>(bufB, w2t, dinv, bufA, M);
    k_agg<false><<<ablk, 256>>>(rowptr, col, (const float2*)bufA, dinv,
                                (const float2*)b2, (float2*)out, M);
}